// round 17
// baseline (speedup 1.0000x reference)
#include <cuda_runtime.h>
#include <cuda_fp16.h>
#include <cstdint>

#define BS_  8
#define N_   4096
#define B_   8
#define R_   64
#define D_   256

#define MTILE   64
#define THREADS 128
#define ROWB    272        // bytes per smem row: 136 fp16 (128 data + 8 pad)
#define NTILES  4096       // total work items
#define GRID    760        // persistent CTAs: 5 per SM on 152 SMs

#define KV_ELEMS (BS_*B_*R_*D_)   // 1,048,576

// ---- smem layout (bytes) ----
#define SMO_AHI  0                      // q chunk fp16 [64][136] = 17408 (later V0)
#define SMO_BB   17408                  // K chunk fp16 [64][136]         (later V1)
#define SMO_PART 34816                  // 256 floats: ssq partials [64][2 chunks][2 halves]
#define SMO_INV  35840                  // 64 floats
#define SMO_TILE 36096                  // 8 bytes: current + next tile index
#define SMEM_TOTAL 36224

// Pre-converted K and a*V (fp16), written by the prelude kernel.
__device__ __half g_Kf[KV_ELEMS];
__device__ __half g_Vf[KV_ELEMS];
__device__ unsigned int g_tileCtr;

// Fast prelude: one float4 of K and V per thread; block 0 presets the work counter
// to GRID (each persistent CTA's first tile is its blockIdx).
__global__ __launch_bounds__(256)
void ProceduralMemory_81535659147884_cvt(const float* __restrict__ K,
                                         const float* __restrict__ V,
                                         const float* __restrict__ a)
{
    if (blockIdx.x == 0 && threadIdx.x == 0) g_tileCtr = GRID;
    const int idx = blockIdx.x * 256 + threadIdx.x;      // per float4
    const float4 k4 = ((const float4*)K)[idx];
    const float4 v4 = ((const float4*)V)[idx];
    const float av = a[idx / (D_ / 4)];
    uint2 kh, vh;
    __half2 t;
    t = __floats2half2_rn(k4.x, k4.y); kh.x = *(uint32_t*)&t;
    t = __floats2half2_rn(k4.z, k4.w); kh.y = *(uint32_t*)&t;
    t = __floats2half2_rn(v4.x * av, v4.y * av); vh.x = *(uint32_t*)&t;
    t = __floats2half2_rn(v4.z * av, v4.w * av); vh.y = *(uint32_t*)&t;
    ((uint2*)g_Kf)[idx] = kh;
    ((uint2*)g_Vf)[idx] = vh;
}

__device__ __forceinline__ uint32_t smem_u32(const void* p) {
    uint32_t a;
    asm("{ .reg .u64 t; cvta.to.shared.u64 t, %1; cvt.u32.u64 %0, t; }" : "=r"(a) : "l"(p));
    return a;
}
__device__ __forceinline__ void cpa16(uint32_t dst, const void* src) {
    asm volatile("cp.async.cg.shared.global [%0], [%1], 16;" :: "r"(dst), "l"(src));
}
__device__ __forceinline__ void ldsm4(uint32_t* r, uint32_t addr) {
    asm volatile("ldmatrix.sync.aligned.m8n8.x4.shared.b16 {%0,%1,%2,%3}, [%4];"
                 : "=r"(r[0]), "=r"(r[1]), "=r"(r[2]), "=r"(r[3]) : "r"(addr));
}
__device__ __forceinline__ void ldsm4t(uint32_t* r, uint32_t addr) {
    asm volatile("ldmatrix.sync.aligned.m8n8.x4.trans.shared.b16 {%0,%1,%2,%3}, [%4];"
                 : "=r"(r[0]), "=r"(r[1]), "=r"(r[2]), "=r"(r[3]) : "r"(addr));
}
__device__ __forceinline__ void mma16816(float* c, const uint32_t* a, const uint32_t* b) {
    asm volatile("mma.sync.aligned.m16n8k16.row.col.f32.f16.f16.f32 "
                 "{%0,%1,%2,%3}, {%4,%5,%6,%7}, {%8,%9}, {%0,%1,%2,%3};"
                 : "+f"(c[0]), "+f"(c[1]), "+f"(c[2]), "+f"(c[3])
                 : "r"(a[0]), "r"(a[1]), "r"(a[2]), "r"(a[3]), "r"(b[0]), "r"(b[1]));
}
__device__ __forceinline__ uint32_t packh2(float x, float y) {
    __half2 h = __floats2half2_rn(x, y);
    return *(uint32_t*)&h;
}
__device__ __forceinline__ void cvt4h(float4 v, uint2& hi) {
    __half hx = __float2half_rn(v.x), hy = __float2half_rn(v.y);
    __half hz = __float2half_rn(v.z), hw = __float2half_rn(v.w);
    hi.x = (uint32_t)__half_as_ushort(hx) | ((uint32_t)__half_as_ushort(hy) << 16);
    hi.y = (uint32_t)__half_as_ushort(hz) | ((uint32_t)__half_as_ushort(hw) << 16);
}
__device__ __forceinline__ void stg_cs(float* p, float2 v) {
    asm volatile("st.global.cs.v2.f32 [%0], {%1,%2};" :: "l"(p), "f"(v.x), "f"(v.y)
                 : "memory");
}

__global__ __launch_bounds__(THREADS, 5)
void ProceduralMemory_81535659147884_kernel(
    const float* __restrict__ q,
    float* __restrict__ out)
{
    extern __shared__ char smc[];
    const uint32_t smb = smem_u32(smc);

    const int tid  = threadIdx.x;
    const int wid  = tid >> 5;        // 0..3
    const int lane = tid & 31;

    float* partS = (float*)(smc + SMO_PART);
    float* invS  = (float*)(smc + SMO_INV);
    unsigned int* tileS = (unsigned int*)(smc + SMO_TILE);

    const uint32_t aOff = (uint32_t)(16 * wid + (lane & 15)) * ROWB +
                          (uint32_t)(lane >> 4) * 16u;
    const uint32_t bOff = (uint32_t)((lane & 7) + ((lane & 16) >> 1)) * ROWB +
                          (uint32_t)((lane >> 3) & 1) * 16u;
    const uint32_t vOff = (uint32_t)(lane & 15) * ROWB + (uint32_t)(lane >> 4) * 16u;

    // First tile: deterministic (blockIdx); stealing starts at GRID.
    unsigned int t = blockIdx.x;

    while (t < NTILES) {
        const int pair = (int)(t >> 6);          // 0..63
        const int tile = (int)(t & 63);          // 0..63
        const int s = pair >> 3, b = pair & 7;
        const int n0 = tile * MTILE;

        // GEMM1 accumulators: warp tile 16 rows x 64 n, persist over 2 K-chunks
        float acc[8][4];
        #pragma unroll
        for (int nt = 0; nt < 8; ++nt)
            #pragma unroll
            for (int i = 0; i < 4; ++i) acc[nt][i] = 0.f;

        #pragma unroll 1
        for (int c = 0; c < 2; ++c) {
            if (c > 0) __syncthreads();   // GEMM1 chunk0 done reading buffers

            // ---- Issue K chunk cp.async first (flies under the q work below) ----
            {
                const __half* ks = g_Kf + (size_t)pair * (R_ * D_) + c * 128;
                #pragma unroll
                for (int g = 0; g < 8; ++g) {
                    const int idx = g * 128 + tid;        // 0..1023
                    const int r = idx >> 4, gc = idx & 15;
                    cpa16(smb + SMO_BB + (uint32_t)r * ROWB + (uint32_t)gc * 16u,
                          ks + (size_t)r * D_ + gc * 8);
                }
                asm volatile("cp.async.commit_group;" ::: "memory");
            }

            // ---- Load q chunk [64 rows, cols 128c..], cvt fp16, ssq partials ----
            {
                const float4* qg = (const float4*)q;
                #pragma unroll 4
                for (int rr = 0; rr < 16; ++rr) {
                    const int m = 16 * wid + rr;
                    float4 v = qg[((size_t)(s * N_ + n0 + m) * B_ + b) * 64 + c * 32 + lane];
                    float ss = v.x * v.x + v.y * v.y + v.z * v.z + v.w * v.w;
                    // depth-4 butterfly: lanes 0 and 16 hold their 16-lane half-sums
                    #pragma unroll
                    for (int o = 8; o; o >>= 1) ss += __shfl_xor_sync(0xFFFFFFFFu, ss, o);
                    if ((lane & 15) == 0) partS[m * 4 + c * 2 + (lane >> 4)] = ss;
                    uint2 hi; cvt4h(v, hi);
                    *(uint2*)(smc + SMO_AHI + (uint32_t)m * ROWB + (uint32_t)lane * 8u) = hi;
                }
            }
            asm volatile("cp.async.wait_group 0;" ::: "memory");
            __syncthreads();

            if (c == 1 && tid < MTILE) {
                const float ss = partS[tid * 4 + 0] + partS[tid * 4 + 1] +
                                 partS[tid * 4 + 2] + partS[tid * 4 + 3];
                invS[tid] = 1.0f / fmaxf(sqrtf(ss), 1e-8f);
            }

            // ---- GEMM1 partial: pure fp16, 1 pass per k-step ----
            #pragma unroll
            for (int k = 0; k < 8; ++k) {
                uint32_t ah[4];
                ldsm4(ah, smb + SMO_AHI + aOff + (uint32_t)k * 32u);
                #pragma unroll
                for (int g = 0; g < 4; ++g) {
                    uint32_t bb[4];
                    ldsm4(bb, smb + SMO_BB + bOff + (uint32_t)g * (16u * ROWB) +
                              (uint32_t)k * 32u);
                    mma16816(acc[2 * g + 0], ah, bb + 0);
                    mma16816(acc[2 * g + 1], ah, bb + 2);
                }
            }
        }
        __syncthreads();   // GEMM1 done reading AHI/BB; invS visible below

        // ---- Issue BOTH V chunks now: V0 -> AHI, V1 -> BB (two commit groups) ----
        {
            const __half* vs = g_Vf + (size_t)pair * (R_ * D_);
            #pragma unroll
            for (int g = 0; g < 8; ++g) {
                const int idx = g * 128 + tid;
                const int r = idx >> 4, gc = idx & 15;
                cpa16(smb + SMO_AHI + (uint32_t)r * ROWB + (uint32_t)gc * 16u,
                      vs + (size_t)r * D_ + gc * 8);
            }
            asm volatile("cp.async.commit_group;" ::: "memory");
            #pragma unroll
            for (int g = 0; g < 8; ++g) {
                const int idx = g * 128 + tid;
                const int r = idx >> 4, gc = idx & 15;
                cpa16(smb + SMO_BB + (uint32_t)r * ROWB + (uint32_t)gc * 16u,
                      vs + (size_t)r * D_ + 128 + gc * 8);
            }
            asm volatile("cp.async.commit_group;" ::: "memory");
        }

        // ---- Prefetch next tile index (ATOMG hides under epilogue1 + GEMM2) ----
        if (tid == 0)
            tileS[0] = atomicAdd(&g_tileCtr, 1u);

        // ---- Epilogue1 (registers only, overlaps V copies):
        //      w = score * inv -> fp16 A-fragments ----
        uint32_t whi[4][4];
        {
            const int r0 = 16 * wid + (lane >> 2);
            const float inv0 = invS[r0], inv1 = invS[r0 + 8];
            #pragma unroll
            for (int kt = 0; kt < 4; ++kt) {
                #pragma unroll
                for (int hf = 0; hf < 2; ++hf) {
                    const int nt = 2 * kt + hf;
                    whi[kt][2 * hf + 0] = packh2(acc[nt][0] * inv0, acc[nt][1] * inv0);
                    whi[kt][2 * hf + 1] = packh2(acc[nt][2] * inv1, acc[nt][3] * inv1);
                }
            }
        }

        // ============ GEMM2: mod[64,256] = W . (a*V); V0 in AHI, V1 in BB ============
        #pragma unroll 1
        for (int j = 0; j < 2; ++j) {
            if (j == 0) {
                asm volatile("cp.async.wait_group 1;" ::: "memory");  // V0 landed
            } else {
                asm volatile("cp.async.wait_group 0;" ::: "memory");  // V1 landed
            }
            __syncthreads();   // cross-thread visibility of the V chunk

            const uint32_t vBase = smb + (j == 0 ? SMO_AHI : SMO_BB) + vOff;

            #pragma unroll 1
            for (int sub = 0; sub < 2; ++sub) {     // 64 output cols at a time
                float acc2[8][4];
                #pragma unroll
                for (int nt = 0; nt < 8; ++nt)
                    #pragma unroll
                    for (int i = 0; i < 4; ++i) acc2[nt][i] = 0.f;

                #pragma unroll
                for (int k = 0; k < 4; ++k) {
                    #pragma unroll
                    for (int g = 0; g < 4; ++g) {
                        uint32_t bb[4];
                        ldsm4t(bb, vBase + (uint32_t)k * (16u * ROWB) +
                                   (uint32_t)sub * 128u + (uint32_t)g * 32u);
                        mma16816(acc2[2 * g + 0], whi[k], bb + 0);
                        mma16816(acc2[2 * g + 1], whi[k], bb + 2);
                    }
                }

                // ---- Epilogue2: out = q * mod (q L2-resident; streaming stores) ----
                #pragma unroll
                for (int h = 0; h < 2; ++h) {
                    const int m = 16 * wid + (lane >> 2) + 8 * h;
                    const size_t gbase = ((size_t)(s * N_ + n0 + m) * B_ + b) * D_;
                    #pragma unroll
                    for (int nt = 0; nt < 8; ++nt) {
                        const int col = 128 * j + 64 * sub + 8 * nt + 2 * (lane & 3);
                        float2 qv = *(const float2*)(q + gbase + col);
                        float2 o;
                        o.x = qv.x * acc2[nt][2 * h];
                        o.y = qv.y * acc2[nt][2 * h + 1];
                        stg_cs(out + gbase + col, o);
                    }
                }
            }
        }

        __syncthreads();             // GEMM2 done reading V; publish prefetched index
        t = tileS[0];
    }
}

extern "C" void kernel_launch(void* const* d_in, const int* in_sizes, int n_in,
                              void* d_out, int out_size)
{
    const float* q    = (const float*)d_in[0];
    const float* pm_K = (const float*)d_in[1];
    const float* pm_V = (const float*)d_in[2];
    const float* pm_a = (const float*)d_in[3];
    float* out = (float*)d_out;

    cudaFuncSetAttribute(ProceduralMemory_81535659147884_kernel,
                         cudaFuncAttributeMaxDynamicSharedMemorySize, SMEM_TOTAL);

    // Prelude: convert K -> fp16, a*V -> fp16 into device scratch; presets work counter.
    ProceduralMemory_81535659147884_cvt<<<KV_ELEMS / 1024, 256>>>(pm_K, pm_V, pm_a);

    // Persistent CTAs: first tile = blockIdx, then atomic work-stealing (prefetched).
    ProceduralMemory_81535659147884_kernel<<<GRID, THREADS, SMEM_TOTAL>>>(q, out);
}